// round 10
// baseline (speedup 1.0000x reference)
#include <cuda_runtime.h>
#include <cuda_bf16.h>

#define DFT  784
#define DP   800
#define PAD  64
#define KC   50
#define LF   6
#define STW  30
#define NCAND 4

#define KDIM 2368          // 3*784 feature planes, padded to 74*32
#define NDIM 1600          // 50 components * 32-stat stride
#define GBM  64
#define GBN  64
#define GBK  32
#define NKT  (KDIM / GBK)  // 74
#define BMAX 2048

typedef unsigned long long u64;

// Exact fp32 tables: c_i = sqrt(invD)*a_i, s = sqrt(invD), nsmu = -s*mu
__device__ __align__(16) float4 g_C0[KC * DP + PAD];   // {c0,c1,c2,c3}
__device__ __align__(16) float4 g_C1[KC * DP + PAD];   // {c4,c5,s,nsmu}
__device__ float g_LD[KC * DP + PAD];
// GEMM operands / output
__device__ __align__(16) __nv_bfloat16 g_F[BMAX * KDIM];
__device__ __align__(16) __nv_bfloat16 g_W[KDIM * NDIM];
__device__ float g_Cout[BMAX * NDIM];
__device__ int   g_cand[BMAX * NCAND];

__device__ __forceinline__ constexpr int IJ(int i, int j) { return i * (i + 1) / 2 + j; }

__device__ __forceinline__ unsigned smem_u32(const void* p) {
    return (unsigned)__cvta_generic_to_shared(p);
}

// ---------------- pack exact tables ----------------
__global__ void pack_tables(const float* __restrict__ A_fac,
                            const float* __restrict__ MU,
                            const float* __restrict__ log_D)
{
    int idx = blockIdx.x * blockDim.x + threadIdx.x;
    if (idx >= KC * DP + PAD) return;
    int k = idx / DP, d = idx - k * DP;
    if (k < KC && d < DFT) {
        int src = k * DFT + d;
        const float* a = A_fac + (size_t)src * LF;
        float ld = log_D[src];
        float s  = expf(-0.5f * ld);
        g_C0[idx] = make_float4(s*a[0], s*a[1], s*a[2], s*a[3]);
        g_C1[idx] = make_float4(s*a[4], s*a[5], s, -s * MU[src]);
        g_LD[idx] = ld;
    } else {
        g_C0[idx] = make_float4(0.f,0.f,0.f,0.f);
        g_C1[idx] = make_float4(0.f,0.f,0.f,0.f);
        g_LD[idx] = 0.f;
    }
}

// ---------------- build F (bf16 features) ----------------
__global__ void build_F(const float* __restrict__ X, const int* __restrict__ J, int B)
{
    int idx = blockIdx.x * blockDim.x + threadIdx.x;
    if (idx >= B * KDIM) return;
    int b = idx / KDIM, col = idx - b * KDIM;
    float v = 0.f;
    if (col < DFT) {
        v = (J[(size_t)b * DFT + col] == 1) ? 1.0f : 0.0f;
    } else if (col < 2 * DFT) {
        int d = col - DFT;
        bool j = (J[(size_t)b * DFT + d] == 1);
        v = j ? X[(size_t)b * DFT + d] : 0.0f;
    } else if (col < 3 * DFT) {
        int d = col - 2 * DFT;
        bool j = (J[(size_t)b * DFT + d] == 1);
        float x = X[(size_t)b * DFT + d];
        v = j ? x * x : 0.0f;
    }
    g_F[idx] = __float2bfloat16(v);
}

// ---------------- build W (bf16 weights) ----------------
__global__ void build_W()
{
    int idx = blockIdx.x * blockDim.x + threadIdx.x;
    if (idx >= KDIM * NDIM) return;
    int r = idx / NDIM, c = idx - r * NDIM;
    int k = c >> 5, st = c & 31;
    float v = 0.f;
    if (st < 29 && r < 3 * DFT) {
        int plane = (r < DFT) ? 0 : ((r < 2 * DFT) ? 1 : 2);
        int d = r - plane * DFT;
        float4 v0 = g_C0[k * DP + d];
        float4 v1 = g_C1[k * DP + d];
        float cc[LF] = {v0.x, v0.y, v0.z, v0.w, v1.x, v1.y};
        float s = v1.z, nsmu = v1.w;
        if (plane == 0) {
            if (st < 21) {
                int i = 0, rem = st;
                while (rem > i) { rem -= (i + 1); i++; }
                v = cc[i] * cc[rem];
            } else if (st < 27) v = nsmu * cc[st - 21];
            else if (st == 27) v = nsmu * nsmu;
            else               v = g_LD[k * DP + d];
        } else if (plane == 1) {
            if (st >= 21 && st < 27) v = s * cc[st - 21];
            else if (st == 27)       v = 2.0f * s * nsmu;
        } else {
            if (st == 27) v = s * s;
        }
    }
    g_W[idx] = __float2bfloat16(v);
}

// ---------------- bf16 GEMM: C = F @ W ----------------
__global__ __launch_bounds__(256, 2)
void gemm_kernel()
{
    __shared__ __align__(16) __nv_bfloat16 As[2][GBM][40];
    __shared__ __align__(16) __nv_bfloat16 Bs[2][GBK][72];

    const int tid  = threadIdx.x;
    const int lane = tid & 31, warp = tid >> 5;
    const int wm = warp & 1, wn = warp >> 1;          // 2 x 4 warp grid
    const int bm = blockIdx.x, bn = blockIdx.y;

    const int ar = tid >> 2, ac = (tid & 3) * 8;      // A tile load coords
    const int br = tid >> 3, bc = (tid & 7) * 8;      // B tile load coords

    const __nv_bfloat16* gA = g_F + (size_t)(bm * GBM + ar) * KDIM + ac;
    const __nv_bfloat16* gB = g_W + (size_t)br * NDIM + bn * GBN + bc;

    float acc[2][2][4];
    #pragma unroll
    for (int mi = 0; mi < 2; mi++)
        #pragma unroll
        for (int ni = 0; ni < 2; ni++)
            #pragma unroll
            for (int u = 0; u < 4; u++) acc[mi][ni][u] = 0.f;

    {
        uint4 fa = *(const uint4*)gA;
        uint4 fb = *(const uint4*)gB;
        *(uint4*)&As[0][ar][ac] = fa;
        *(uint4*)&Bs[0][br][bc] = fb;
    }
    __syncthreads();

    for (int kt = 0; kt < NKT; kt++) {
        const int cur = kt & 1;
        uint4 na, nb;
        if (kt + 1 < NKT) {
            na = *(const uint4*)(gA + (size_t)(kt + 1) * GBK);
            nb = *(const uint4*)(gB + (size_t)(kt + 1) * GBK * NDIM);
        }
        #pragma unroll
        for (int ks = 0; ks < 2; ks++) {
            unsigned a[2][4], b[2][2];
            #pragma unroll
            for (int mi = 0; mi < 2; mi++) {
                unsigned addr = smem_u32(&As[cur][wm*32 + mi*16 + (lane & 15)]
                                            [ks*16 + ((lane >> 4) << 3)]);
                asm volatile("ldmatrix.sync.aligned.m8n8.x4.shared.b16 {%0,%1,%2,%3}, [%4];"
                             : "=r"(a[mi][0]), "=r"(a[mi][1]), "=r"(a[mi][2]), "=r"(a[mi][3])
                             : "r"(addr));
            }
            #pragma unroll
            for (int ni = 0; ni < 2; ni++) {
                unsigned addr = smem_u32(&Bs[cur][ks*16 + (lane & 15)][wn*16 + ni*8]);
                asm volatile("ldmatrix.sync.aligned.m8n8.x2.trans.shared.b16 {%0,%1}, [%2];"
                             : "=r"(b[ni][0]), "=r"(b[ni][1])
                             : "r"(addr));
            }
            #pragma unroll
            for (int mi = 0; mi < 2; mi++)
                #pragma unroll
                for (int ni = 0; ni < 2; ni++) {
                    asm volatile(
                        "mma.sync.aligned.m16n8k16.row.col.f32.bf16.bf16.f32 "
                        "{%0,%1,%2,%3}, {%4,%5,%6,%7}, {%8,%9}, {%0,%1,%2,%3};"
                        : "+f"(acc[mi][ni][0]), "+f"(acc[mi][ni][1]),
                          "+f"(acc[mi][ni][2]), "+f"(acc[mi][ni][3])
                        : "r"(a[mi][0]), "r"(a[mi][1]), "r"(a[mi][2]), "r"(a[mi][3]),
                          "r"(b[ni][0]), "r"(b[ni][1]));
                }
        }
        if (kt + 1 < NKT) {
            __syncthreads();
            *(uint4*)&As[cur ^ 1][ar][ac] = na;
            *(uint4*)&Bs[cur ^ 1][br][bc] = nb;
            __syncthreads();
        }
    }

    #pragma unroll
    for (int mi = 0; mi < 2; mi++)
        #pragma unroll
        for (int ni = 0; ni < 2; ni++) {
            int row = bm * GBM + wm * 32 + mi * 16 + (lane >> 2);
            int col = bn * GBN + wn * 16 + ni * 8 + (lane & 3) * 2;
            float* p = g_Cout + (size_t)row * NDIM + col;
            p[0] = acc[mi][ni][0]; p[1] = acc[mi][ni][1];
            float* p2 = p + 8 * NDIM;
            p2[0] = acc[mi][ni][2]; p2[1] = acc[mi][ni][3];
        }
}

// ---------------- small linalg helpers ----------------
__device__ __forceinline__ float chol6(float* S, float* inv)
{
    float prod = 1.f;
    #pragma unroll
    for (int j = 0; j < LF; j++) {
        float s = S[IJ(j, j)];
        #pragma unroll
        for (int m = 0; m < j; m++) s = fmaf(-S[IJ(j, m)], S[IJ(j, m)], s);
        prod *= s;
        float rs = rsqrtf(s);
        inv[j] = rs;
        S[IJ(j, j)] = s * rs;
        #pragma unroll
        for (int i = j + 1; i < LF; i++) {
            float t = S[IJ(i, j)];
            #pragma unroll
            for (int m = 0; m < j; m++) t = fmaf(-S[IJ(i, m)], S[IJ(j, m)], t);
            S[IJ(i, j)] = t * rs;
        }
    }
    return prod;
}

__device__ __forceinline__ float fwd6(const float* L, const float* inv, const float* q, float* y)
{
    float ysq = 0.f;
    #pragma unroll
    for (int i = 0; i < LF; i++) {
        float t = q[i];
        #pragma unroll
        for (int m = 0; m < i; m++) t = fmaf(-L[IJ(i, m)], y[m], t);
        y[i] = t * inv[i];
        ysq = fmaf(y[i], y[i], ysq);
    }
    return ysq;
}

// ---------------- approx score + top-4 select (warp per sample) ----------------
__global__ __launch_bounds__(128, 8)
void score_select(const float* __restrict__ PI, int B)
{
    const int lane = threadIdx.x & 31;
    const int warp = threadIdx.x >> 5;
    const int b = blockIdx.x * 4 + warp;
    if (b >= B) return;

    float sc[2] = {-1e30f, -1e30f};
    int   kk[2] = {lane, lane + 32};
    #pragma unroll
    for (int si = 0; si < 2; si++) {
        int k = kk[si];
        if (k < KC) {
            const float* st = g_Cout + (size_t)b * NDIM + k * 32;
            float P[21], q[LF];
            #pragma unroll
            for (int u = 0; u < 21; u++) P[u] = st[u];
            #pragma unroll
            for (int i = 0; i < LF; i++) { P[IJ(i, i)] += 1.0f; q[i] = st[21 + i]; }
            float inv[LF];
            float prod = chol6(P, inv);
            float y[LF];
            float ysq = fwd6(P, inv, q, y);
            float s = PI[k] - 0.5f * (st[27] - ysq + __logf(prod) + st[28]);
            if (s == s) sc[si] = s;           // NaN guard
        }
    }
    #pragma unroll
    for (int r = 0; r < NCAND; r++) {
        float m; int mk;
        if (sc[0] >= sc[1]) { m = sc[0]; mk = kk[0]; } else { m = sc[1]; mk = kk[1]; }
        #pragma unroll
        for (int off = 16; off; off >>= 1) {
            float om = __shfl_xor_sync(0xffffffffu, m, off);
            int   ok = __shfl_xor_sync(0xffffffffu, mk, off);
            if (om > m || (om == m && ok < mk)) { m = om; mk = ok; }
        }
        if (lane == 0) g_cand[b * NCAND + r] = mk;
        if (kk[0] == mk) sc[0] = -2e30f;
        if (kk[1] == mk) sc[1] = -2e30f;
    }
}

// ---------------- exact rescore + linalg + epilogue (block per sample) ----------------
__global__ __launch_bounds__(128, 4)
void rescore_final(const float* __restrict__ X, const int* __restrict__ J,
                   const float* __restrict__ MU, const float* __restrict__ A_fac,
                   const float* __restrict__ log_D, const float* __restrict__ PI,
                   float* __restrict__ outPw, float* __restrict__ outM,
                   float* __restrict__ outA, float* __restrict__ outD)
{
    __shared__ float s_ex[NCAND][STW];   // [0..28] stats, [29] score
    __shared__ float s_mz[LF], s_Lz[21];
    __shared__ int   s_c;

    const int b    = blockIdx.x;
    const int tid  = threadIdx.x;
    const int lane = tid & 31;
    const int warp = tid >> 5;

    // each warp: exact fp32 stats for its candidate
    {
        const int k = g_cand[b * NCAND + warp];
        const float4* __restrict__ p0 = g_C0 + (size_t)k * DP;
        const float4* __restrict__ p1 = g_C1 + (size_t)k * DP;
        const float*  __restrict__ pl = g_LD + (size_t)k * DP;

        float a[29];
        #pragma unroll
        for (int u = 0; u < 29; u++) a[u] = 0.f;

        for (int d = lane; d < DFT; d += 32) {
            float4 v0 = p0[d], v1 = p1[d];
            float ldv = pl[d];
            bool  jo  = (J[(size_t)b * DFT + d] == 1);
            float jf  = jo ? 1.0f : 0.0f;
            float xj  = jo ? X[(size_t)b * DFT + d] : 0.0f;
            float c[LF] = {v0.x, v0.y, v0.z, v0.w, v1.x, v1.y};
            float e = fmaf(v1.w, jf, v1.z * xj);
            a[27] = fmaf(e, e, a[27]);
            a[28] = fmaf(jf, ldv, a[28]);
            #pragma unroll
            for (int i = 0; i < LF; i++) {
                a[21 + i] = fmaf(e, c[i], a[21 + i]);
                float jc = jf * c[i];
                #pragma unroll
                for (int j = 0; j <= i; j++)
                    a[IJ(i, j)] = fmaf(jc, c[j], a[IJ(i, j)]);
            }
        }
        #pragma unroll
        for (int u = 0; u < 29; u++) {
            float v = a[u];
            #pragma unroll
            for (int off = 16; off > 0; off >>= 1)
                v += __shfl_xor_sync(0xffffffffu, v, off);
            a[u] = v;
        }
        if (lane == 0) {
            float P[21], q[LF];
            #pragma unroll
            for (int u = 0; u < 21; u++) P[u] = a[u];
            #pragma unroll
            for (int i = 0; i < LF; i++) { P[IJ(i, i)] += 1.0f; q[i] = a[21 + i]; }
            float inv[LF];
            float prod = chol6(P, inv);
            float y[LF];
            float ysq = fwd6(P, inv, q, y);
            #pragma unroll
            for (int u = 0; u < 29; u++) s_ex[warp][u] = a[u];
            s_ex[warp][29] = PI[k] - 0.5f * (a[27] - ysq + __logf(prod) + a[28]);
        }
    }
    __syncthreads();

    if (tid == 0) {
        int wc = 0; float best = -1e30f;
        #pragma unroll
        for (int w = 0; w < NCAND; w++)
            if (s_ex[w][29] > best) { best = s_ex[w][29]; wc = w; }
        s_c = g_cand[b * NCAND + wc];

        float P[21], q[LF];
        #pragma unroll
        for (int u = 0; u < 21; u++) P[u] = s_ex[wc][u];
        #pragma unroll
        for (int i = 0; i < LF; i++) { P[IJ(i, i)] += 1.0f; q[i] = s_ex[wc][21 + i]; }

        float inv[LF];
        (void)chol6(P, inv);
        float y[LF];
        (void)fwd6(P, inv, q, y);
        float mz[LF];
        #pragma unroll
        for (int ii = LF - 1; ii >= 0; ii--) {
            float t = y[ii];
            #pragma unroll
            for (int m = ii + 1; m < LF; m++) t = fmaf(-P[IJ(m, ii)], mz[m], t);
            mz[ii] = t * inv[ii];
        }
        float Li[21];
        #pragma unroll
        for (int j = 0; j < LF; j++) {
            Li[IJ(j, j)] = inv[j];
            #pragma unroll
            for (int i = j + 1; i < LF; i++) {
                float t = 0.f;
                #pragma unroll
                for (int m = j; m < i; m++) t = fmaf(P[IJ(i, m)], Li[IJ(m, j)], t);
                Li[IJ(i, j)] = -inv[i] * t;
            }
        }
        float C[21];
        #pragma unroll
        for (int i = 0; i < LF; i++)
            #pragma unroll
            for (int j = 0; j <= i; j++) {
                float t = 0.f;
                #pragma unroll
                for (int m = i; m < LF; m++) t = fmaf(Li[IJ(m, i)], Li[IJ(m, j)], t);
                C[IJ(i, j)] = t;
            }
        float invz[LF];
        (void)chol6(C, invz);
        #pragma unroll
        for (int i = 0; i < LF; i++) s_mz[i] = mz[i];
        #pragma unroll
        for (int u = 0; u < 21; u++) s_Lz[u] = C[u];
        outPw[b] = 1.0f;
    }
    __syncthreads();

    const int c = s_c;
    float mz[LF], Lz[21];
    #pragma unroll
    for (int i = 0; i < LF; i++) mz[i] = s_mz[i];
    #pragma unroll
    for (int u = 0; u < 21; u++) Lz[u] = s_Lz[u];
    const float* __restrict__ ac  = A_fac + (size_t)c * DFT * LF;
    const float* __restrict__ muc = MU    + (size_t)c * DFT;
    const float* __restrict__ ldc = log_D + (size_t)c * DFT;
    for (int d = tid; d < DFT; d += 128) {
        const float2* ar = reinterpret_cast<const float2*>(ac + (size_t)d * LF);
        float2 r0 = ar[0], r1 = ar[1], r2 = ar[2];
        float a[LF] = {r0.x, r0.y, r1.x, r1.y, r2.x, r2.y};
        float Mo = muc[d];
        #pragma unroll
        for (int i = 0; i < LF; i++) Mo = fmaf(a[i], mz[i], Mo);
        outM[(size_t)b * DFT + d] = Mo;
        float Ao[LF];
        #pragma unroll
        for (int j = 0; j < LF; j++) {
            float s = 0.f;
            #pragma unroll
            for (int i = j; i < LF; i++) s = fmaf(a[i], Lz[IJ(i, j)], s);
            Ao[j] = s;
        }
        float2* pA = reinterpret_cast<float2*>(outA + ((size_t)b * DFT + d) * LF);
        pA[0] = make_float2(Ao[0], Ao[1]);
        pA[1] = make_float2(Ao[2], Ao[3]);
        pA[2] = make_float2(Ao[4], Ao[5]);
        outD[(size_t)b * DFT + d] = expf(ldc[d]);
    }
}

extern "C" void kernel_launch(void* const* d_in, const int* in_sizes, int n_in,
                              void* d_out, int out_size)
{
    const float* X      = (const float*)d_in[0];
    const int*   J      = (const int*)  d_in[1];
    const float* MU     = (const float*)d_in[2];
    const float* A_fac  = (const float*)d_in[3];
    const float* log_D  = (const float*)d_in[4];
    const float* PI     = (const float*)d_in[5];
    float* out = (float*)d_out;

    const int B = in_sizes[0] / DFT;     // 2048
    float* outPw = out;
    float* outM  = out + B;
    float* outA  = outM + (size_t)B * DFT;
    float* outD  = outA + (size_t)B * DFT * LF;

    pack_tables<<<(KC * DP + PAD + 255) / 256, 256>>>(A_fac, MU, log_D);
    build_F<<<(B * KDIM + 255) / 256, 256>>>(X, J, B);
    build_W<<<(KDIM * NDIM + 255) / 256, 256>>>();
    dim3 gg(B / GBM, NDIM / GBN);
    gemm_kernel<<<gg, 256>>>();
    score_select<<<(B + 3) / 4, 128>>>(PI, B);
    rescore_final<<<B, 128>>>(X, J, MU, A_fac, log_D, PI, outPw, outM, outA, outD);
}

// round 13
// speedup vs baseline: 1.2314x; 1.2314x over previous
#include <cuda_runtime.h>
#include <cuda_bf16.h>

#define DFT  784
#define DP   800
#define PAD  64
#define KC   50
#define LF   6
#define STW  30
#define NCAND 4

#define KDIM 2368          // 3*784 feature planes, padded to 74*32
#define NDIM 1600          // 50 components * 32-stat stride
#define BM   128
#define BN   64
#define BK   32
#define NKT  (KDIM / BK)   // 74
#define NSTAGE 3
#define BMAX 2048

typedef unsigned long long u64;

// Exact fp32 tables: c_i = sqrt(invD)*a_i, s = sqrt(invD), nsmu = -s*mu
__device__ __align__(16) float4 g_C0[KC * DP + PAD];   // {c0,c1,c2,c3}
__device__ __align__(16) float4 g_C1[KC * DP + PAD];   // {c4,c5,s,nsmu}
__device__ float g_LD[KC * DP + PAD];
// GEMM operands / output
__device__ __align__(16) __nv_bfloat16 g_F[BMAX * KDIM];
__device__ __align__(16) __nv_bfloat16 g_W[KDIM * NDIM];
__device__ float g_Cout[BMAX * NDIM];
__device__ int   g_cand[BMAX * NCAND];

__device__ __forceinline__ constexpr int IJ(int i, int j) { return i * (i + 1) / 2 + j; }

__device__ __forceinline__ unsigned smem_u32(const void* p) {
    return (unsigned)__cvta_generic_to_shared(p);
}
#define CP_ASYNC16(dst, src) \
    asm volatile("cp.async.cg.shared.global [%0], [%1], 16;\n" :: "r"(dst), "l"(src))
#define CP_COMMIT() asm volatile("cp.async.commit_group;\n" ::)
#define CP_WAIT1()  asm volatile("cp.async.wait_group 1;\n" ::)

// ---------------- pack exact tables ----------------
__global__ void pack_tables(const float* __restrict__ A_fac,
                            const float* __restrict__ MU,
                            const float* __restrict__ log_D)
{
    int idx = blockIdx.x * blockDim.x + threadIdx.x;
    if (idx >= KC * DP + PAD) return;
    int k = idx / DP, d = idx - k * DP;
    if (k < KC && d < DFT) {
        int src = k * DFT + d;
        const float* a = A_fac + (size_t)src * LF;
        float ld = log_D[src];
        float s  = expf(-0.5f * ld);
        g_C0[idx] = make_float4(s*a[0], s*a[1], s*a[2], s*a[3]);
        g_C1[idx] = make_float4(s*a[4], s*a[5], s, -s * MU[src]);
        g_LD[idx] = ld;
    } else {
        g_C0[idx] = make_float4(0.f,0.f,0.f,0.f);
        g_C1[idx] = make_float4(0.f,0.f,0.f,0.f);
        g_LD[idx] = 0.f;
    }
}

// ---------------- build F (bf16 features) ----------------
__global__ void build_F(const float* __restrict__ X, const int* __restrict__ J, int B)
{
    int idx = blockIdx.x * blockDim.x + threadIdx.x;
    if (idx >= B * KDIM) return;
    int b = idx / KDIM, col = idx - b * KDIM;
    float v = 0.f;
    if (col < DFT) {
        v = (J[(size_t)b * DFT + col] == 1) ? 1.0f : 0.0f;
    } else if (col < 2 * DFT) {
        int d = col - DFT;
        bool j = (J[(size_t)b * DFT + d] == 1);
        v = j ? X[(size_t)b * DFT + d] : 0.0f;
    } else if (col < 3 * DFT) {
        int d = col - 2 * DFT;
        bool j = (J[(size_t)b * DFT + d] == 1);
        float x = X[(size_t)b * DFT + d];
        v = j ? x * x : 0.0f;
    }
    g_F[idx] = __float2bfloat16(v);
}

// ---------------- build W (bf16 weights) ----------------
__global__ void build_W()
{
    int idx = blockIdx.x * blockDim.x + threadIdx.x;
    if (idx >= KDIM * NDIM) return;
    int r = idx / NDIM, c = idx - r * NDIM;
    int k = c >> 5, st = c & 31;
    float v = 0.f;
    if (st < 29 && r < 3 * DFT) {
        int plane = (r < DFT) ? 0 : ((r < 2 * DFT) ? 1 : 2);
        int d = r - plane * DFT;
        float4 v0 = g_C0[k * DP + d];
        float4 v1 = g_C1[k * DP + d];
        float cc[LF] = {v0.x, v0.y, v0.z, v0.w, v1.x, v1.y};
        float s = v1.z, nsmu = v1.w;
        if (plane == 0) {
            if (st < 21) {
                int i = 0, rem = st;
                while (rem > i) { rem -= (i + 1); i++; }
                v = cc[i] * cc[rem];
            } else if (st < 27) v = nsmu * cc[st - 21];
            else if (st == 27) v = nsmu * nsmu;
            else               v = g_LD[k * DP + d];
        } else if (plane == 1) {
            if (st >= 21 && st < 27) v = s * cc[st - 21];
            else if (st == 27)       v = 2.0f * s * nsmu;
        } else {
            if (st == 27) v = s * s;
        }
    }
    g_W[idx] = __float2bfloat16(v);
}

// ---------------- bf16 GEMM: C = F @ W (cp.async 3-stage, 128x64x32) ----------------
__global__ __launch_bounds__(256, 2)
void gemm_kernel()
{
    __shared__ __align__(16) __nv_bfloat16 As[NSTAGE][BM][40];
    __shared__ __align__(16) __nv_bfloat16 Bs[NSTAGE][BK][72];

    const int tid  = threadIdx.x;
    const int lane = tid & 31, warp = tid >> 5;
    const int wm = warp >> 1, wn = warp & 1;          // 4 x 2 warp grid, warp tile 32x32
    const int bm = blockIdx.x, bn = blockIdx.y;

    const int ar = tid >> 2, ac = (tid & 3) * 8;      // A: 2 chunks/thread (rows ar, ar+64)
    const int br = tid >> 3, bc = (tid & 7) * 8;      // B: 1 chunk/thread

    const __nv_bfloat16* gA = g_F + (size_t)(bm * BM + ar) * KDIM + ac;
    const __nv_bfloat16* gB = g_W + (size_t)br * NDIM + bn * BN + bc;

    float acc[2][4][4];
    #pragma unroll
    for (int mi = 0; mi < 2; mi++)
        #pragma unroll
        for (int ni = 0; ni < 4; ni++)
            #pragma unroll
            for (int u = 0; u < 4; u++) acc[mi][ni][u] = 0.f;

    // preload stages 0..NSTAGE-2
    #pragma unroll
    for (int s = 0; s < NSTAGE - 1; s++) {
        const __nv_bfloat16* pa = gA + (size_t)s * BK;
        CP_ASYNC16(smem_u32(&As[s][ar][ac]), pa);
        CP_ASYNC16(smem_u32(&As[s][ar + 64][ac]), pa + (size_t)64 * KDIM);
        CP_ASYNC16(smem_u32(&Bs[s][br][bc]), gB + (size_t)s * BK * NDIM);
        CP_COMMIT();
    }

    int buf = 0;
    for (int kt = 0; kt < NKT; kt++) {
        CP_WAIT1();
        __syncthreads();

        // issue stage kt+2 into the buffer freed at iteration kt-1
        if (kt + NSTAGE - 1 < NKT) {
            int nb = buf + 2; if (nb >= NSTAGE) nb -= NSTAGE;
            const __nv_bfloat16* pa = gA + (size_t)(kt + 2) * BK;
            CP_ASYNC16(smem_u32(&As[nb][ar][ac]), pa);
            CP_ASYNC16(smem_u32(&As[nb][ar + 64][ac]), pa + (size_t)64 * KDIM);
            CP_ASYNC16(smem_u32(&Bs[nb][br][bc]), gB + (size_t)(kt + 2) * BK * NDIM);
        }
        CP_COMMIT();

        #pragma unroll
        for (int ks = 0; ks < 2; ks++) {
            unsigned a[2][4], b[2][4];
            #pragma unroll
            for (int mi = 0; mi < 2; mi++) {
                unsigned addr = smem_u32(&As[buf][wm*32 + mi*16 + (lane & 15)]
                                            [ks*16 + ((lane >> 4) << 3)]);
                asm volatile("ldmatrix.sync.aligned.m8n8.x4.shared.b16 {%0,%1,%2,%3}, [%4];"
                             : "=r"(a[mi][0]), "=r"(a[mi][1]), "=r"(a[mi][2]), "=r"(a[mi][3])
                             : "r"(addr));
            }
            #pragma unroll
            for (int nj = 0; nj < 2; nj++) {
                unsigned addr = smem_u32(&Bs[buf][ks*16 + (lane & 15)]
                                            [wn*32 + nj*16 + ((lane >> 4) << 3)]);
                asm volatile("ldmatrix.sync.aligned.m8n8.x4.trans.shared.b16 {%0,%1,%2,%3}, [%4];"
                             : "=r"(b[nj][0]), "=r"(b[nj][1]), "=r"(b[nj][2]), "=r"(b[nj][3])
                             : "r"(addr));
            }
            #pragma unroll
            for (int mi = 0; mi < 2; mi++)
                #pragma unroll
                for (int nj = 0; nj < 2; nj++) {
                    asm volatile(
                        "mma.sync.aligned.m16n8k16.row.col.f32.bf16.bf16.f32 "
                        "{%0,%1,%2,%3}, {%4,%5,%6,%7}, {%8,%9}, {%0,%1,%2,%3};"
                        : "+f"(acc[mi][nj*2][0]), "+f"(acc[mi][nj*2][1]),
                          "+f"(acc[mi][nj*2][2]), "+f"(acc[mi][nj*2][3])
                        : "r"(a[mi][0]), "r"(a[mi][1]), "r"(a[mi][2]), "r"(a[mi][3]),
                          "r"(b[nj][0]), "r"(b[nj][1]));
                    asm volatile(
                        "mma.sync.aligned.m16n8k16.row.col.f32.bf16.bf16.f32 "
                        "{%0,%1,%2,%3}, {%4,%5,%6,%7}, {%8,%9}, {%0,%1,%2,%3};"
                        : "+f"(acc[mi][nj*2+1][0]), "+f"(acc[mi][nj*2+1][1]),
                          "+f"(acc[mi][nj*2+1][2]), "+f"(acc[mi][nj*2+1][3])
                        : "r"(a[mi][0]), "r"(a[mi][1]), "r"(a[mi][2]), "r"(a[mi][3]),
                          "r"(b[nj][2]), "r"(b[nj][3]));
                }
        }
        __syncthreads();
        buf++; if (buf >= NSTAGE) buf = 0;
    }

    #pragma unroll
    for (int mi = 0; mi < 2; mi++)
        #pragma unroll
        for (int ni = 0; ni < 4; ni++) {
            int row = bm * BM + wm * 32 + mi * 16 + (lane >> 2);
            int col = bn * BN + wn * 32 + ni * 8 + (lane & 3) * 2;
            float* p = g_Cout + (size_t)row * NDIM + col;
            p[0] = acc[mi][ni][0]; p[1] = acc[mi][ni][1];
            float* p2 = p + 8 * NDIM;
            p2[0] = acc[mi][ni][2]; p2[1] = acc[mi][ni][3];
        }
}

// ---------------- small linalg helpers ----------------
__device__ __forceinline__ float chol6(float* S, float* inv)
{
    float prod = 1.f;
    #pragma unroll
    for (int j = 0; j < LF; j++) {
        float s = S[IJ(j, j)];
        #pragma unroll
        for (int m = 0; m < j; m++) s = fmaf(-S[IJ(j, m)], S[IJ(j, m)], s);
        prod *= s;
        float rs = rsqrtf(s);
        inv[j] = rs;
        S[IJ(j, j)] = s * rs;
        #pragma unroll
        for (int i = j + 1; i < LF; i++) {
            float t = S[IJ(i, j)];
            #pragma unroll
            for (int m = 0; m < j; m++) t = fmaf(-S[IJ(i, m)], S[IJ(j, m)], t);
            S[IJ(i, j)] = t * rs;
        }
    }
    return prod;
}

__device__ __forceinline__ float fwd6(const float* L, const float* inv, const float* q, float* y)
{
    float ysq = 0.f;
    #pragma unroll
    for (int i = 0; i < LF; i++) {
        float t = q[i];
        #pragma unroll
        for (int m = 0; m < i; m++) t = fmaf(-L[IJ(i, m)], y[m], t);
        y[i] = t * inv[i];
        ysq = fmaf(y[i], y[i], ysq);
    }
    return ysq;
}

// ---------------- approx score + top-4 select (warp per sample) ----------------
__global__ __launch_bounds__(128, 8)
void score_select(const float* __restrict__ PI, int B)
{
    const int lane = threadIdx.x & 31;
    const int warp = threadIdx.x >> 5;
    const int b = blockIdx.x * 4 + warp;
    if (b >= B) return;

    float sc[2] = {-1e30f, -1e30f};
    int   kk[2] = {lane, lane + 32};
    #pragma unroll
    for (int si = 0; si < 2; si++) {
        int k = kk[si];
        if (k < KC) {
            const float* st = g_Cout + (size_t)b * NDIM + k * 32;
            float P[21], q[LF];
            #pragma unroll
            for (int u = 0; u < 21; u++) P[u] = st[u];
            #pragma unroll
            for (int i = 0; i < LF; i++) { P[IJ(i, i)] += 1.0f; q[i] = st[21 + i]; }
            float inv[LF];
            float prod = chol6(P, inv);
            float y[LF];
            float ysq = fwd6(P, inv, q, y);
            float s = PI[k] - 0.5f * (st[27] - ysq + __logf(prod) + st[28]);
            if (s == s) sc[si] = s;           // NaN guard
        }
    }
    #pragma unroll
    for (int r = 0; r < NCAND; r++) {
        float m; int mk;
        if (sc[0] >= sc[1]) { m = sc[0]; mk = kk[0]; } else { m = sc[1]; mk = kk[1]; }
        #pragma unroll
        for (int off = 16; off; off >>= 1) {
            float om = __shfl_xor_sync(0xffffffffu, m, off);
            int   ok = __shfl_xor_sync(0xffffffffu, mk, off);
            if (om > m || (om == m && ok < mk)) { m = om; mk = ok; }
        }
        if (lane == 0) g_cand[b * NCAND + r] = mk;
        if (kk[0] == mk) sc[0] = -2e30f;
        if (kk[1] == mk) sc[1] = -2e30f;
    }
}

// ---------------- exact rescore + linalg + epilogue (block per sample) ----------------
__global__ __launch_bounds__(128, 4)
void rescore_final(const float* __restrict__ X, const int* __restrict__ J,
                   const float* __restrict__ MU, const float* __restrict__ A_fac,
                   const float* __restrict__ log_D, const float* __restrict__ PI,
                   float* __restrict__ outPw, float* __restrict__ outM,
                   float* __restrict__ outA, float* __restrict__ outD)
{
    __shared__ float s_ex[NCAND][STW];   // [0..28] stats, [29] score
    __shared__ float s_mz[LF], s_Lz[21];
    __shared__ int   s_c;

    const int b    = blockIdx.x;
    const int tid  = threadIdx.x;
    const int lane = tid & 31;
    const int warp = tid >> 5;

    {
        const int k = g_cand[b * NCAND + warp];
        const float4* __restrict__ p0 = g_C0 + (size_t)k * DP;
        const float4* __restrict__ p1 = g_C1 + (size_t)k * DP;
        const float*  __restrict__ pl = g_LD + (size_t)k * DP;

        float a[29];
        #pragma unroll
        for (int u = 0; u < 29; u++) a[u] = 0.f;

        for (int d = lane; d < DFT; d += 32) {
            float4 v0 = p0[d], v1 = p1[d];
            float ldv = pl[d];
            bool  jo  = (J[(size_t)b * DFT + d] == 1);
            float jf  = jo ? 1.0f : 0.0f;
            float xj  = jo ? X[(size_t)b * DFT + d] : 0.0f;
            float c[LF] = {v0.x, v0.y, v0.z, v0.w, v1.x, v1.y};
            float e = fmaf(v1.w, jf, v1.z * xj);
            a[27] = fmaf(e, e, a[27]);
            a[28] = fmaf(jf, ldv, a[28]);
            #pragma unroll
            for (int i = 0; i < LF; i++) {
                a[21 + i] = fmaf(e, c[i], a[21 + i]);
                float jc = jf * c[i];
                #pragma unroll
                for (int j = 0; j <= i; j++)
                    a[IJ(i, j)] = fmaf(jc, c[j], a[IJ(i, j)]);
            }
        }
        #pragma unroll
        for (int u = 0; u < 29; u++) {
            float v = a[u];
            #pragma unroll
            for (int off = 16; off > 0; off >>= 1)
                v += __shfl_xor_sync(0xffffffffu, v, off);
            a[u] = v;
        }
        if (lane == 0) {
            float P[21], q[LF];
            #pragma unroll
            for (int u = 0; u < 21; u++) P[u] = a[u];
            #pragma unroll
            for (int i = 0; i < LF; i++) { P[IJ(i, i)] += 1.0f; q[i] = a[21 + i]; }
            float inv[LF];
            float prod = chol6(P, inv);
            float y[LF];
            float ysq = fwd6(P, inv, q, y);
            #pragma unroll
            for (int u = 0; u < 29; u++) s_ex[warp][u] = a[u];
            s_ex[warp][29] = PI[k] - 0.5f * (a[27] - ysq + __logf(prod) + a[28]);
        }
    }
    __syncthreads();

    if (tid == 0) {
        int wc = 0; float best = -1e30f;
        #pragma unroll
        for (int w = 0; w < NCAND; w++)
            if (s_ex[w][29] > best) { best = s_ex[w][29]; wc = w; }
        s_c = g_cand[b * NCAND + wc];

        float P[21], q[LF];
        #pragma unroll
        for (int u = 0; u < 21; u++) P[u] = s_ex[wc][u];
        #pragma unroll
        for (int i = 0; i < LF; i++) { P[IJ(i, i)] += 1.0f; q[i] = s_ex[wc][21 + i]; }

        float inv[LF];
        (void)chol6(P, inv);
        float y[LF];
        (void)fwd6(P, inv, q, y);
        float mz[LF];
        #pragma unroll
        for (int ii = LF - 1; ii >= 0; ii--) {
            float t = y[ii];
            #pragma unroll
            for (int m = ii + 1; m < LF; m++) t = fmaf(-P[IJ(m, ii)], mz[m], t);
            mz[ii] = t * inv[ii];
        }
        float Li[21];
        #pragma unroll
        for (int j = 0; j < LF; j++) {
            Li[IJ(j, j)] = inv[j];
            #pragma unroll
            for (int i = j + 1; i < LF; i++) {
                float t = 0.f;
                #pragma unroll
                for (int m = j; m < i; m++) t = fmaf(P[IJ(i, m)], Li[IJ(m, j)], t);
                Li[IJ(i, j)] = -inv[i] * t;
            }
        }
        float C[21];
        #pragma unroll
        for (int i = 0; i < LF; i++)
            #pragma unroll
            for (int j = 0; j <= i; j++) {
                float t = 0.f;
                #pragma unroll
                for (int m = i; m < LF; m++) t = fmaf(Li[IJ(m, i)], Li[IJ(m, j)], t);
                C[IJ(i, j)] = t;
            }
        float invz[LF];
        (void)chol6(C, invz);
        #pragma unroll
        for (int i = 0; i < LF; i++) s_mz[i] = mz[i];
        #pragma unroll
        for (int u = 0; u < 21; u++) s_Lz[u] = C[u];
        outPw[b] = 1.0f;
    }
    __syncthreads();

    const int c = s_c;
    float mz[LF], Lz[21];
    #pragma unroll
    for (int i = 0; i < LF; i++) mz[i] = s_mz[i];
    #pragma unroll
    for (int u = 0; u < 21; u++) Lz[u] = s_Lz[u];
    const float* __restrict__ ac  = A_fac + (size_t)c * DFT * LF;
    const float* __restrict__ muc = MU    + (size_t)c * DFT;
    const float* __restrict__ ldc = log_D + (size_t)c * DFT;
    for (int d = tid; d < DFT; d += 128) {
        const float2* ar = reinterpret_cast<const float2*>(ac + (size_t)d * LF);
        float2 r0 = ar[0], r1 = ar[1], r2 = ar[2];
        float a[LF] = {r0.x, r0.y, r1.x, r1.y, r2.x, r2.y};
        float Mo = muc[d];
        #pragma unroll
        for (int i = 0; i < LF; i++) Mo = fmaf(a[i], mz[i], Mo);
        outM[(size_t)b * DFT + d] = Mo;
        float Ao[LF];
        #pragma unroll
        for (int j = 0; j < LF; j++) {
            float s = 0.f;
            #pragma unroll
            for (int i = j; i < LF; i++) s = fmaf(a[i], Lz[IJ(i, j)], s);
            Ao[j] = s;
        }
        float2* pA = reinterpret_cast<float2*>(outA + ((size_t)b * DFT + d) * LF);
        pA[0] = make_float2(Ao[0], Ao[1]);
        pA[1] = make_float2(Ao[2], Ao[3]);
        pA[2] = make_float2(Ao[4], Ao[5]);
        outD[(size_t)b * DFT + d] = expf(ldc[d]);
    }
}

extern "C" void kernel_launch(void* const* d_in, const int* in_sizes, int n_in,
                              void* d_out, int out_size)
{
    const float* X      = (const float*)d_in[0];
    const int*   J      = (const int*)  d_in[1];
    const float* MU     = (const float*)d_in[2];
    const float* A_fac  = (const float*)d_in[3];
    const float* log_D  = (const float*)d_in[4];
    const float* PI     = (const float*)d_in[5];
    float* out = (float*)d_out;

    const int B = in_sizes[0] / DFT;     // 2048
    float* outPw = out;
    float* outM  = out + B;
    float* outA  = outM + (size_t)B * DFT;
    float* outD  = outA + (size_t)B * DFT * LF;

    pack_tables<<<(KC * DP + PAD + 255) / 256, 256>>>(A_fac, MU, log_D);
    build_F<<<(B * KDIM + 255) / 256, 256>>>(X, J, B);
    build_W<<<(KDIM * NDIM + 255) / 256, 256>>>();
    dim3 gg(B / BM, NDIM / BN);
    gemm_kernel<<<gg, 256>>>();
    score_select<<<(B + 3) / 4, 128>>>(PI, B);
    rescore_final<<<B, 128>>>(X, J, MU, A_fac, log_D, PI, outPw, outM, outA, outD);
}

// round 14
// speedup vs baseline: 1.4366x; 1.1667x over previous
#include <cuda_runtime.h>
#include <cuda_bf16.h>

#define DFT  784
#define DP   800
#define PAD  64
#define KC   50
#define LF   6
#define STW  30
#define NCAND 4

#define K1   800            // jf plane (784 + pad)
#define N1   1600           // 50 k * 32-stat stride (P21,q_ns6,nsmu2,ld)
#define K2   1600           // xj plane (800) + xj^2 plane (800)
#define N2   448            // 50 k * 8-stat stride (q_s6, cross, s2), padded to 7*64
#define BM   128
#define BN   64
#define BK   32
#define NSTAGE 3
#define BMAX 2048

typedef unsigned long long u64;

// Exact fp32 tables: c_i = sqrt(invD)*a_i, s = sqrt(invD), nsmu = -s*mu
__device__ __align__(16) float4 g_C0[KC * DP + PAD];
__device__ __align__(16) float4 g_C1[KC * DP + PAD];
__device__ float g_LD[KC * DP + PAD];
// GEMM operands / outputs
__device__ __align__(16) __nv_bfloat16 g_F1[BMAX * K1];
__device__ __align__(16) __nv_bfloat16 g_F2[BMAX * K2];
__device__ __align__(16) __nv_bfloat16 g_W1[K1 * N1];
__device__ __align__(16) __nv_bfloat16 g_W2[K2 * N2];
__device__ float g_Cout1[BMAX * N1];
__device__ float g_Cout2[BMAX * N2];
__device__ int   g_cand[BMAX * NCAND];

__device__ __forceinline__ constexpr int IJ(int i, int j) { return i * (i + 1) / 2 + j; }

__device__ __forceinline__ unsigned smem_u32(const void* p) {
    return (unsigned)__cvta_generic_to_shared(p);
}
#define CP_ASYNC16(dst, src) \
    asm volatile("cp.async.cg.shared.global [%0], [%1], 16;\n" :: "r"(dst), "l"(src))
#define CP_COMMIT() asm volatile("cp.async.commit_group;\n" ::)
#define CP_WAIT1()  asm volatile("cp.async.wait_group 1;\n" ::)

// ---------------- pack exact tables ----------------
__global__ void pack_tables(const float* __restrict__ A_fac,
                            const float* __restrict__ MU,
                            const float* __restrict__ log_D)
{
    int idx = blockIdx.x * blockDim.x + threadIdx.x;
    if (idx >= KC * DP + PAD) return;
    int k = idx / DP, d = idx - k * DP;
    if (k < KC && d < DFT) {
        int src = k * DFT + d;
        const float* a = A_fac + (size_t)src * LF;
        float ld = log_D[src];
        float s  = expf(-0.5f * ld);
        g_C0[idx] = make_float4(s*a[0], s*a[1], s*a[2], s*a[3]);
        g_C1[idx] = make_float4(s*a[4], s*a[5], s, -s * MU[src]);
        g_LD[idx] = ld;
    } else {
        g_C0[idx] = make_float4(0.f,0.f,0.f,0.f);
        g_C1[idx] = make_float4(0.f,0.f,0.f,0.f);
        g_LD[idx] = 0.f;
    }
}

// ---------------- build F1 (jf) and F2 (xj | xj^2) ----------------
__global__ void build_F(const float* __restrict__ X, const int* __restrict__ J, int B)
{
    int idx = blockIdx.x * blockDim.x + threadIdx.x;
    if (idx >= B * DP) return;
    int b = idx / DP, d = idx - b * DP;
    float jf = 0.f, xj = 0.f;
    if (d < DFT) {
        bool jo = (J[(size_t)b * DFT + d] == 1);
        jf = jo ? 1.0f : 0.0f;
        xj = jo ? X[(size_t)b * DFT + d] : 0.0f;
    }
    g_F1[(size_t)b * K1 + d]       = __float2bfloat16(jf);
    g_F2[(size_t)b * K2 + d]       = __float2bfloat16(xj);
    g_F2[(size_t)b * K2 + DP + d]  = __float2bfloat16(xj * xj);
}

// ---------------- build W1 [K1 x N1] ----------------
__global__ void build_W1()
{
    int idx = blockIdx.x * blockDim.x + threadIdx.x;
    if (idx >= K1 * N1) return;
    int r = idx / N1, c = idx - r * N1;
    int k = c >> 5, st = c & 31;
    float v = 0.f;
    if (r < DFT && st < 29) {
        float4 v0 = g_C0[k * DP + r];
        float4 v1 = g_C1[k * DP + r];
        float cc[LF] = {v0.x, v0.y, v0.z, v0.w, v1.x, v1.y};
        float nsmu = v1.w;
        if (st < 21) {
            int i = 0, rem = st;
            while (rem > i) { rem -= (i + 1); i++; }
            v = cc[i] * cc[rem];
        } else if (st < 27) v = nsmu * cc[st - 21];
        else if (st == 27)  v = nsmu * nsmu;
        else                v = g_LD[k * DP + r];
    }
    g_W1[idx] = __float2bfloat16(v);
}

// ---------------- build W2 [K2 x N2] ----------------
__global__ void build_W2()
{
    int idx = blockIdx.x * blockDim.x + threadIdx.x;
    if (idx >= K2 * N2) return;
    int r = idx / N2, c = idx - r * N2;
    int k = c >> 3, st = c & 7;
    float v = 0.f;
    if (k < KC) {
        if (r < DFT) {                       // xj plane
            float4 v0 = g_C0[k * DP + r];
            float4 v1 = g_C1[k * DP + r];
            float cc[LF] = {v0.x, v0.y, v0.z, v0.w, v1.x, v1.y};
            if (st < 6)       v = v1.z * cc[st];          // s * c_i
            else if (st == 6) v = 2.0f * v1.z * v1.w;     // 2 s nsmu
        } else if (r >= DP && r < DP + DFT) {             // xj^2 plane
            int d = r - DP;
            float s = g_C1[k * DP + d].z;
            if (st == 7) v = s * s;
        }
    }
    g_W2[idx] = __float2bfloat16(v);
}

// ---------------- generic bf16 GEMM: C = A @ W (cp.async 3-stage, 128x64x32) ----------------
__global__ __launch_bounds__(256, 2)
void gemm_kernel(const __nv_bfloat16* __restrict__ A,
                 const __nv_bfloat16* __restrict__ W,
                 float* __restrict__ C, int kdim, int ndim, int nkt)
{
    __shared__ __align__(16) __nv_bfloat16 As[NSTAGE][BM][40];
    __shared__ __align__(16) __nv_bfloat16 Bs[NSTAGE][BK][72];

    const int tid  = threadIdx.x;
    const int lane = tid & 31, warp = tid >> 5;
    const int wm = warp >> 1, wn = warp & 1;
    const int bm = blockIdx.x, bn = blockIdx.y;

    const int ar = tid >> 2, ac = (tid & 3) * 8;
    const int br = tid >> 3, bc = (tid & 7) * 8;

    const __nv_bfloat16* gA = A + (size_t)(bm * BM + ar) * kdim + ac;
    const __nv_bfloat16* gB = W + (size_t)br * ndim + bn * BN + bc;

    float acc[2][4][4];
    #pragma unroll
    for (int mi = 0; mi < 2; mi++)
        #pragma unroll
        for (int ni = 0; ni < 4; ni++)
            #pragma unroll
            for (int u = 0; u < 4; u++) acc[mi][ni][u] = 0.f;

    #pragma unroll
    for (int s = 0; s < NSTAGE - 1; s++) {
        const __nv_bfloat16* pa = gA + (size_t)s * BK;
        CP_ASYNC16(smem_u32(&As[s][ar][ac]), pa);
        CP_ASYNC16(smem_u32(&As[s][ar + 64][ac]), pa + (size_t)64 * kdim);
        CP_ASYNC16(smem_u32(&Bs[s][br][bc]), gB + (size_t)s * BK * ndim);
        CP_COMMIT();
    }

    int buf = 0;
    for (int kt = 0; kt < nkt; kt++) {
        CP_WAIT1();
        __syncthreads();

        if (kt + NSTAGE - 1 < nkt) {
            int nb = buf + 2; if (nb >= NSTAGE) nb -= NSTAGE;
            const __nv_bfloat16* pa = gA + (size_t)(kt + 2) * BK;
            CP_ASYNC16(smem_u32(&As[nb][ar][ac]), pa);
            CP_ASYNC16(smem_u32(&As[nb][ar + 64][ac]), pa + (size_t)64 * kdim);
            CP_ASYNC16(smem_u32(&Bs[nb][br][bc]), gB + (size_t)(kt + 2) * BK * ndim);
        }
        CP_COMMIT();

        #pragma unroll
        for (int ks = 0; ks < 2; ks++) {
            unsigned a[2][4], b[2][4];
            #pragma unroll
            for (int mi = 0; mi < 2; mi++) {
                unsigned addr = smem_u32(&As[buf][wm*32 + mi*16 + (lane & 15)]
                                            [ks*16 + ((lane >> 4) << 3)]);
                asm volatile("ldmatrix.sync.aligned.m8n8.x4.shared.b16 {%0,%1,%2,%3}, [%4];"
                             : "=r"(a[mi][0]), "=r"(a[mi][1]), "=r"(a[mi][2]), "=r"(a[mi][3])
                             : "r"(addr));
            }
            #pragma unroll
            for (int nj = 0; nj < 2; nj++) {
                unsigned addr = smem_u32(&Bs[buf][ks*16 + (lane & 15)]
                                            [wn*32 + nj*16 + ((lane >> 4) << 3)]);
                asm volatile("ldmatrix.sync.aligned.m8n8.x4.trans.shared.b16 {%0,%1,%2,%3}, [%4];"
                             : "=r"(b[nj][0]), "=r"(b[nj][1]), "=r"(b[nj][2]), "=r"(b[nj][3])
                             : "r"(addr));
            }
            #pragma unroll
            for (int mi = 0; mi < 2; mi++)
                #pragma unroll
                for (int nj = 0; nj < 2; nj++) {
                    asm volatile(
                        "mma.sync.aligned.m16n8k16.row.col.f32.bf16.bf16.f32 "
                        "{%0,%1,%2,%3}, {%4,%5,%6,%7}, {%8,%9}, {%0,%1,%2,%3};"
                        : "+f"(acc[mi][nj*2][0]), "+f"(acc[mi][nj*2][1]),
                          "+f"(acc[mi][nj*2][2]), "+f"(acc[mi][nj*2][3])
                        : "r"(a[mi][0]), "r"(a[mi][1]), "r"(a[mi][2]), "r"(a[mi][3]),
                          "r"(b[nj][0]), "r"(b[nj][1]));
                    asm volatile(
                        "mma.sync.aligned.m16n8k16.row.col.f32.bf16.bf16.f32 "
                        "{%0,%1,%2,%3}, {%4,%5,%6,%7}, {%8,%9}, {%0,%1,%2,%3};"
                        : "+f"(acc[mi][nj*2+1][0]), "+f"(acc[mi][nj*2+1][1]),
                          "+f"(acc[mi][nj*2+1][2]), "+f"(acc[mi][nj*2+1][3])
                        : "r"(a[mi][0]), "r"(a[mi][1]), "r"(a[mi][2]), "r"(a[mi][3]),
                          "r"(b[nj][2]), "r"(b[nj][3]));
                }
        }
        __syncthreads();
        buf++; if (buf >= NSTAGE) buf = 0;
    }

    #pragma unroll
    for (int mi = 0; mi < 2; mi++)
        #pragma unroll
        for (int ni = 0; ni < 4; ni++) {
            int row = bm * BM + wm * 32 + mi * 16 + (lane >> 2);
            int col = bn * BN + wn * 32 + ni * 8 + (lane & 3) * 2;
            float* p = C + (size_t)row * ndim + col;
            p[0] = acc[mi][ni][0]; p[1] = acc[mi][ni][1];
            float* p2 = p + 8 * ndim;
            p2[0] = acc[mi][ni][2]; p2[1] = acc[mi][ni][3];
        }
}

// ---------------- small linalg helpers ----------------
__device__ __forceinline__ float chol6(float* S, float* inv)
{
    float prod = 1.f;
    #pragma unroll
    for (int j = 0; j < LF; j++) {
        float s = S[IJ(j, j)];
        #pragma unroll
        for (int m = 0; m < j; m++) s = fmaf(-S[IJ(j, m)], S[IJ(j, m)], s);
        prod *= s;
        float rs = rsqrtf(s);
        inv[j] = rs;
        S[IJ(j, j)] = s * rs;
        #pragma unroll
        for (int i = j + 1; i < LF; i++) {
            float t = S[IJ(i, j)];
            #pragma unroll
            for (int m = 0; m < j; m++) t = fmaf(-S[IJ(i, m)], S[IJ(j, m)], t);
            S[IJ(i, j)] = t * rs;
        }
    }
    return prod;
}

__device__ __forceinline__ float fwd6(const float* L, const float* inv, const float* q, float* y)
{
    float ysq = 0.f;
    #pragma unroll
    for (int i = 0; i < LF; i++) {
        float t = q[i];
        #pragma unroll
        for (int m = 0; m < i; m++) t = fmaf(-L[IJ(i, m)], y[m], t);
        y[i] = t * inv[i];
        ysq = fmaf(y[i], y[i], ysq);
    }
    return ysq;
}

// ---------------- approx score + top-4 select (warp per sample) ----------------
__global__ __launch_bounds__(128, 8)
void score_select(const float* __restrict__ PI, int B)
{
    const int lane = threadIdx.x & 31;
    const int warp = threadIdx.x >> 5;
    const int b = blockIdx.x * 4 + warp;
    if (b >= B) return;

    float sc[2] = {-1e30f, -1e30f};
    int   kk[2] = {lane, lane + 32};
    #pragma unroll
    for (int si = 0; si < 2; si++) {
        int k = kk[si];
        if (k < KC) {
            const float* s1 = g_Cout1 + (size_t)b * N1 + k * 32;
            const float* s2 = g_Cout2 + (size_t)b * N2 + k * 8;
            float P[21], q[LF];
            #pragma unroll
            for (int u = 0; u < 21; u++) P[u] = s1[u];
            #pragma unroll
            for (int i = 0; i < LF; i++) { P[IJ(i, i)] += 1.0f; q[i] = s1[21 + i] + s2[i]; }
            float quad = s1[27] + s2[6] + s2[7];
            float jld  = s1[28];
            float inv[LF];
            float prod = chol6(P, inv);
            float y[LF];
            float ysq = fwd6(P, inv, q, y);
            float s = PI[k] - 0.5f * (quad - ysq + __logf(prod) + jld);
            if (s == s) sc[si] = s;           // NaN guard
        }
    }
    #pragma unroll
    for (int r = 0; r < NCAND; r++) {
        float m; int mk;
        if (sc[0] >= sc[1]) { m = sc[0]; mk = kk[0]; } else { m = sc[1]; mk = kk[1]; }
        #pragma unroll
        for (int off = 16; off; off >>= 1) {
            float om = __shfl_xor_sync(0xffffffffu, m, off);
            int   ok = __shfl_xor_sync(0xffffffffu, mk, off);
            if (om > m || (om == m && ok < mk)) { m = om; mk = ok; }
        }
        if (lane == 0) g_cand[b * NCAND + r] = mk;
        if (kk[0] == mk) sc[0] = -2e30f;
        if (kk[1] == mk) sc[1] = -2e30f;
    }
}

// ---------------- exact rescore + linalg + epilogue (block per sample) ----------------
__global__ __launch_bounds__(128, 4)
void rescore_final(const float* __restrict__ X, const int* __restrict__ J,
                   const float* __restrict__ MU, const float* __restrict__ A_fac,
                   const float* __restrict__ log_D, const float* __restrict__ PI,
                   float* __restrict__ outPw, float* __restrict__ outM,
                   float* __restrict__ outA, float* __restrict__ outD)
{
    __shared__ float s_ex[NCAND][STW];
    __shared__ float s_mz[LF], s_Lz[21];
    __shared__ int   s_c;

    const int b    = blockIdx.x;
    const int tid  = threadIdx.x;
    const int lane = tid & 31;
    const int warp = tid >> 5;

    {
        const int k = g_cand[b * NCAND + warp];
        const float4* __restrict__ p0 = g_C0 + (size_t)k * DP;
        const float4* __restrict__ p1 = g_C1 + (size_t)k * DP;
        const float*  __restrict__ pl = g_LD + (size_t)k * DP;

        float a[29];
        #pragma unroll
        for (int u = 0; u < 29; u++) a[u] = 0.f;

        for (int d = lane; d < DFT; d += 32) {
            float4 v0 = p0[d], v1 = p1[d];
            float ldv = pl[d];
            bool  jo  = (J[(size_t)b * DFT + d] == 1);
            float jf  = jo ? 1.0f : 0.0f;
            float xj  = jo ? X[(size_t)b * DFT + d] : 0.0f;
            float c[LF] = {v0.x, v0.y, v0.z, v0.w, v1.x, v1.y};
            float e = fmaf(v1.w, jf, v1.z * xj);
            a[27] = fmaf(e, e, a[27]);
            a[28] = fmaf(jf, ldv, a[28]);
            #pragma unroll
            for (int i = 0; i < LF; i++) {
                a[21 + i] = fmaf(e, c[i], a[21 + i]);
                float jc = jf * c[i];
                #pragma unroll
                for (int j = 0; j <= i; j++)
                    a[IJ(i, j)] = fmaf(jc, c[j], a[IJ(i, j)]);
            }
        }
        #pragma unroll
        for (int u = 0; u < 29; u++) {
            float v = a[u];
            #pragma unroll
            for (int off = 16; off > 0; off >>= 1)
                v += __shfl_xor_sync(0xffffffffu, v, off);
            a[u] = v;
        }
        if (lane == 0) {
            float P[21], q[LF];
            #pragma unroll
            for (int u = 0; u < 21; u++) P[u] = a[u];
            #pragma unroll
            for (int i = 0; i < LF; i++) { P[IJ(i, i)] += 1.0f; q[i] = a[21 + i]; }
            float inv[LF];
            float prod = chol6(P, inv);
            float y[LF];
            float ysq = fwd6(P, inv, q, y);
            #pragma unroll
            for (int u = 0; u < 29; u++) s_ex[warp][u] = a[u];
            s_ex[warp][29] = PI[k] - 0.5f * (a[27] - ysq + __logf(prod) + a[28]);
        }
    }
    __syncthreads();

    if (tid == 0) {
        int wc = 0; float best = -1e30f;
        #pragma unroll
        for (int w = 0; w < NCAND; w++)
            if (s_ex[w][29] > best) { best = s_ex[w][29]; wc = w; }
        s_c = g_cand[b * NCAND + wc];

        float P[21], q[LF];
        #pragma unroll
        for (int u = 0; u < 21; u++) P[u] = s_ex[wc][u];
        #pragma unroll
        for (int i = 0; i < LF; i++) { P[IJ(i, i)] += 1.0f; q[i] = s_ex[wc][21 + i]; }

        float inv[LF];
        (void)chol6(P, inv);
        float y[LF];
        (void)fwd6(P, inv, q, y);
        float mz[LF];
        #pragma unroll
        for (int ii = LF - 1; ii >= 0; ii--) {
            float t = y[ii];
            #pragma unroll
            for (int m = ii + 1; m < LF; m++) t = fmaf(-P[IJ(m, ii)], mz[m], t);
            mz[ii] = t * inv[ii];
        }
        float Li[21];
        #pragma unroll
        for (int j = 0; j < LF; j++) {
            Li[IJ(j, j)] = inv[j];
            #pragma unroll
            for (int i = j + 1; i < LF; i++) {
                float t = 0.f;
                #pragma unroll
                for (int m = j; m < i; m++) t = fmaf(P[IJ(i, m)], Li[IJ(m, j)], t);
                Li[IJ(i, j)] = -inv[i] * t;
            }
        }
        float C[21];
        #pragma unroll
        for (int i = 0; i < LF; i++)
            #pragma unroll
            for (int j = 0; j <= i; j++) {
                float t = 0.f;
                #pragma unroll
                for (int m = i; m < LF; m++) t = fmaf(Li[IJ(m, i)], Li[IJ(m, j)], t);
                C[IJ(i, j)] = t;
            }
        float invz[LF];
        (void)chol6(C, invz);
        #pragma unroll
        for (int i = 0; i < LF; i++) s_mz[i] = mz[i];
        #pragma unroll
        for (int u = 0; u < 21; u++) s_Lz[u] = C[u];
        outPw[b] = 1.0f;
    }
    __syncthreads();

    const int c = s_c;
    float mz[LF], Lz[21];
    #pragma unroll
    for (int i = 0; i < LF; i++) mz[i] = s_mz[i];
    #pragma unroll
    for (int u = 0; u < 21; u++) Lz[u] = s_Lz[u];
    const float* __restrict__ ac  = A_fac + (size_t)c * DFT * LF;
    const float* __restrict__ muc = MU    + (size_t)c * DFT;
    const float* __restrict__ ldc = log_D + (size_t)c * DFT;
    for (int d = tid; d < DFT; d += 128) {
        const float2* ar = reinterpret_cast<const float2*>(ac + (size_t)d * LF);
        float2 r0 = ar[0], r1 = ar[1], r2 = ar[2];
        float a[LF] = {r0.x, r0.y, r1.x, r1.y, r2.x, r2.y};
        float Mo = muc[d];
        #pragma unroll
        for (int i = 0; i < LF; i++) Mo = fmaf(a[i], mz[i], Mo);
        outM[(size_t)b * DFT + d] = Mo;
        float Ao[LF];
        #pragma unroll
        for (int j = 0; j < LF; j++) {
            float s = 0.f;
            #pragma unroll
            for (int i = j; i < LF; i++) s = fmaf(a[i], Lz[IJ(i, j)], s);
            Ao[j] = s;
        }
        float2* pA = reinterpret_cast<float2*>(outA + ((size_t)b * DFT + d) * LF);
        pA[0] = make_float2(Ao[0], Ao[1]);
        pA[1] = make_float2(Ao[2], Ao[3]);
        pA[2] = make_float2(Ao[4], Ao[5]);
        outD[(size_t)b * DFT + d] = expf(ldc[d]);
    }
}

extern "C" void kernel_launch(void* const* d_in, const int* in_sizes, int n_in,
                              void* d_out, int out_size)
{
    const float* X      = (const float*)d_in[0];
    const int*   J      = (const int*)  d_in[1];
    const float* MU     = (const float*)d_in[2];
    const float* A_fac  = (const float*)d_in[3];
    const float* log_D  = (const float*)d_in[4];
    const float* PI     = (const float*)d_in[5];
    float* out = (float*)d_out;

    const int B = in_sizes[0] / DFT;     // 2048
    float* outPw = out;
    float* outM  = out + B;
    float* outA  = outM + (size_t)B * DFT;
    float* outD  = outA + (size_t)B * DFT * LF;

    pack_tables<<<(KC * DP + PAD + 255) / 256, 256>>>(A_fac, MU, log_D);
    build_F<<<(B * DP + 255) / 256, 256>>>(X, J, B);
    build_W1<<<(K1 * N1 + 255) / 256, 256>>>();
    build_W2<<<(K2 * N2 + 255) / 256, 256>>>();

    __nv_bfloat16 *pF1, *pF2, *pW1, *pW2;
    float *pC1, *pC2;
    cudaGetSymbolAddress((void**)&pF1, g_F1);
    cudaGetSymbolAddress((void**)&pF2, g_F2);
    cudaGetSymbolAddress((void**)&pW1, g_W1);
    cudaGetSymbolAddress((void**)&pW2, g_W2);
    cudaGetSymbolAddress((void**)&pC1, g_Cout1);
    cudaGetSymbolAddress((void**)&pC2, g_Cout2);

    dim3 gg1(B / BM, N1 / BN);
    gemm_kernel<<<gg1, 256>>>(pF1, pW1, pC1, K1, N1, K1 / BK);
    dim3 gg2(B / BM, N2 / BN);
    gemm_kernel<<<gg2, 256>>>(pF2, pW2, pC2, K2, N2, K2 / BK);

    score_select<<<(B + 3) / 4, 128>>>(PI, B);
    rescore_final<<<B, 128>>>(X, J, MU, A_fac, log_D, PI, outPw, outM, outA, outD);
}